// round 15
// baseline (speedup 1.0000x reference)
#include <cuda_runtime.h>
#include <cstdint>

// LSTM(B=8192, T=1024, H=10, in=1) -> final cell state c_T -> Linear(10,1).
//
// R14: BATCH-PAIR f32x2 decomposition. Every f32x2 pair is (batchA, batchB):
//  * lane r owns unit r for TWO batches; state h2 = (h'A_r, h'B_r) is a
//    natural pair -> one STS.64 serves both batches (no duplication).
//  * h-table entries (hA_k, hB_k) feed FFMA2 against DUPLICATED weights
//    (w,w) -- duplication is free at init since weights load once.
//  * gate accumulators are (preA, preB): zero horizontal adds; c/h update
//    fully packed.
// Per warp: 3 groups x 2 batches = 6 batches; ~71 instr + 6 MIO per step
// = 11.8 instr + 1.0 MIO per batch (champion R13: 12.3 + 2.0). MIO per SM
// halves -> LSU 4-cyc issue floor (the suspected binder at ~440cyc/step)
// drops to ~220.
//
// Kept: tanh.approx.f32; sigma folded into pre-scaled weights; h' = 2h;
// double-buffered parity table; no per-step sync (intra-warp exchange);
// 80B group stride (16B-aligned, broadcast reads conflict-free, stores
// max 2-way).

#define B_TOT 8192
#define T_LEN 1024
#define HID   10
#define GPW   3                    // groups per warp
#define WPB   2                    // warps per block
#define THREADS (WPB * 32)
#define BATCH_PER_BLOCK (WPB * GPW * 2)   // 12
#define GSTRIDE 20                 // floats per group (80B = 10 pairs)

typedef unsigned long long ull;

__device__ __forceinline__ ull pack2(float x, float y) {
    ull r;
    asm("mov.b64 %0, {%1, %2};" : "=l"(r) : "f"(x), "f"(y));
    return r;
}
__device__ __forceinline__ ull ffma2(ull a, ull b, ull c) {
    ull d;
    asm("fma.rn.f32x2 %0, %1, %2, %3;" : "=l"(d) : "l"(a), "l"(b), "l"(c));
    return d;
}
__device__ __forceinline__ ull fmul2(ull a, ull b) {
    ull d;
    asm("mul.rn.f32x2 %0, %1, %2;" : "=l"(d) : "l"(a), "l"(b));
    return d;
}
__device__ __forceinline__ float ftanh(float x) {
    float r;
    asm("tanh.approx.f32 %0, %1;" : "=f"(r) : "f"(x));
    return r;
}
__device__ __forceinline__ void lds_v2b64(uint32_t addr, ull& a, ull& b) {
    asm volatile("ld.shared.v2.b64 {%0, %1}, [%2];" : "=l"(a), "=l"(b) : "r"(addr));
}
__device__ __forceinline__ void sts_b64(uint32_t addr, ull v) {
    asm volatile("st.shared.b64 [%0], %1;" :: "r"(addr), "l"(v) : "memory");
}
__device__ __forceinline__ uint32_t smem_u32(const void* p) {
    uint32_t a;
    asm("{ .reg .u64 t; cvta.to.shared.u64 t, %1; cvt.u32.u64 %0, t; }"
        : "=r"(a) : "l"(p));
    return a;
}

__global__ __launch_bounds__(THREADS)
void lstm_lin_kernel(const float* __restrict__ x,       // [B, T, 1]
                     const float* __restrict__ W_ih,    // [4H, 1]
                     const float* __restrict__ W_hh,    // [4H, H]
                     const float* __restrict__ b_ih,    // [4H]
                     const float* __restrict__ b_hh,    // [4H]
                     const float* __restrict__ W_lin,   // [1, H]
                     const float* __restrict__ b_lin,   // [1]
                     float* __restrict__ out)           // [B, 1]
{
    // [parity][warp][group][10 pairs]; pair k = (h'A_k, h'B_k) at +k*8.
    __shared__ float hbuf[2][WPB][GPW][GSTRIDE];

    const int warp  = threadIdx.x >> 5;
    const int wlane = threadIdx.x & 31;
    const int group = wlane / HID;           // 0..2 active; 3 => lanes 30,31
    const int r     = wlane - group * HID;   // unit 0..9
    const int base  = group * HID;
    const bool active = (group < GPW);
    const int sgrp   = active ? group : 0;

    const int wglob  = blockIdx.x * WPB + warp;
    const int batchA = wglob * (GPW * 2) + group * 2;
    const int batchB = batchA + 1;
    const bool validA = active && (batchA < B_TOT);
    const bool validB = active && (batchB < B_TOT);
    const int bA = validA ? batchA : 0;
    const int bB = validB ? batchB : 0;

    // ---- weights: DUPLICATED pairs (w,w), pre-scaled ----
    // gate g in {i,f,g,o}: sg = 0.5 (sigmoid) / 1.0 (tanh gate);
    // extra 0.5 on W_hh because the carried state is h' = 2h.
    ull wd[4][HID], wihd[4], bd[4];
#pragma unroll
    for (int g = 0; g < 4; g++) {
        const float sg = (g == 2) ? 1.0f : 0.5f;
        const int row = g * HID + r;
#pragma unroll
        for (int k = 0; k < HID; k++) {
            const float s = W_hh[row * HID + k] * sg * 0.5f;
            wd[g][k] = pack2(s, s);
        }
        const float wi = W_ih[row] * sg;
        const float bb = (b_ih[row] + b_hh[row]) * sg;
        wihd[g] = pack2(wi, wi);
        bd[g]   = pack2(bb, bb);
    }

    const ull H2 = pack2(0.5f, 0.5f);
    ull c2 = pack2(0.0f, 0.0f);              // (cA_r, cB_r)

    const uint32_t smem0 = smem_u32(&hbuf[0][0][0][0]);
    const uint32_t grp_base0 = smem0 + (uint32_t)(warp * GPW + sgrp) * (GSTRIDE * 4);
    const uint32_t grp_base1 = grp_base0 + WPB * GPW * GSTRIDE * 4;   // parity-1
    const uint32_t slot0 = grp_base0 + r * 8;
    const uint32_t slot1 = grp_base1 + r * 8;

    if (active) sts_b64(slot0, 0ULL);
    __syncwarp();

    const float4* __restrict__ xrowA =
        reinterpret_cast<const float4*>(x + (size_t)bA * T_LEN);
    const float4* __restrict__ xrowB =
        reinterpret_cast<const float4*>(x + (size_t)bB * T_LEN);

    for (int t4 = 0; t4 < T_LEN / 4; t4++) {
        const float4 xqA = __ldg(&xrowA[t4]);
        const float4 xqB = __ldg(&xrowB[t4]);
        const float xsA[4] = {xqA.x, xqA.y, xqA.z, xqA.w};
        const float xsB[4] = {xqB.x, xqB.y, xqB.z, xqB.w};

#pragma unroll
        for (int jt = 0; jt < 4; jt++) {
            const uint32_t rd = (jt & 1) ? grp_base1 : grp_base0;
            const uint32_t wr = (jt & 1) ? slot0 : slot1;

            // 5x LDS.128 -> 10 batch-pairs (hA_k, hB_k); broadcast reads
            ull hd[HID];
            lds_v2b64(rd +  0, hd[0], hd[1]);
            lds_v2b64(rd + 16, hd[2], hd[3]);
            lds_v2b64(rd + 32, hd[4], hd[5]);
            lds_v2b64(rd + 48, hd[6], hd[7]);
            lds_v2b64(rd + 64, hd[8], hd[9]);

            const ull xx = pack2(xsA[jt], xsB[jt]);

            ull acc0 = ffma2(xx, wihd[0], bd[0]);
            ull acc1 = ffma2(xx, wihd[1], bd[1]);
            ull acc2 = ffma2(xx, wihd[2], bd[2]);
            ull acc3 = ffma2(xx, wihd[3], bd[3]);
#pragma unroll
            for (int k = 0; k < HID; k++) {
                acc0 = ffma2(wd[0][k], hd[k], acc0);
                acc1 = ffma2(wd[1][k], hd[k], acc1);
                acc2 = ffma2(wd[2][k], hd[k], acc2);
                acc3 = ffma2(wd[3][k], hd[k], acc3);
            }

            // halves alias the accumulators: .x = batch A, .y = batch B
            const float2 gi = *reinterpret_cast<const float2*>(&acc0);
            const float2 gf = *reinterpret_cast<const float2*>(&acc1);
            const float2 gg = *reinterpret_cast<const float2*>(&acc2);
            const float2 go = *reinterpret_cast<const float2*>(&acc3);
            const ull ti2 = pack2(ftanh(gi.x), ftanh(gi.y));
            const ull tf2 = pack2(ftanh(gf.x), ftanh(gf.y));
            const ull tg2 = pack2(ftanh(gg.x), ftanh(gg.y));
            const ull to2 = pack2(ftanh(go.x), ftanh(go.y));

            // c = sigma_f*c + sigma_i*tanh_g  (packed; sigma = 0.5+0.5t)
            const ull sf2 = ffma2(H2, tf2, H2);
            const ull si2 = ffma2(H2, ti2, H2);
            c2 = ffma2(sf2, c2, fmul2(si2, tg2));

            // h' = 2h = (1 + tanh_o) * tanh(c); the pair IS the store
            const float2 cc = *reinterpret_cast<const float2*>(&c2);
            const ull tc2 = pack2(ftanh(cc.x), ftanh(cc.y));
            const ull h2 = ffma2(to2, tc2, tc2);
            if (active) sts_b64(wr, h2);

            asm volatile("" ::: "memory");   // pin STS(t) before LDS(t+1)
        }
    }

    // ---- epilogue: out[b] = sum_u c[u] * W_lin[u] + b_lin ----
    const float2 cc = *reinterpret_cast<const float2*>(&c2);
    const float wl = W_lin[r];
    float pA = cc.x * wl, pB = cc.y * wl;
    float sA = pA, sB = pB;
#pragma unroll
    for (int j = 1; j < HID; j++) {
        sA += __shfl_sync(0xffffffffu, pA, base + j);
        sB += __shfl_sync(0xffffffffu, pB, base + j);
    }

    if (validA && r == 0) out[batchA] = sA + b_lin[0];
    if (validB && r == 0) out[batchB] = sB + b_lin[0];
}

extern "C" void kernel_launch(void* const* d_in, const int* in_sizes, int n_in,
                              void* d_out, int out_size) {
    const float* x     = (const float*)d_in[0];
    const float* W_ih  = (const float*)d_in[1];
    const float* W_hh  = (const float*)d_in[2];
    const float* b_ih  = (const float*)d_in[3];
    const float* b_hh  = (const float*)d_in[4];
    const float* W_lin = (const float*)d_in[5];
    const float* b_lin = (const float*)d_in[6];
    float* out = (float*)d_out;

    const int blocks = (B_TOT + BATCH_PER_BLOCK - 1) / BATCH_PER_BLOCK;  // 683
    lstm_lin_kernel<<<blocks, THREADS>>>(
        x, W_ih, W_hh, b_ih, b_hh, W_lin, b_lin, out);
}